// round 12
// baseline (speedup 1.0000x reference)
#include <cuda_runtime.h>
#include <cuda_bf16.h>
#include <math.h>
#include <stdint.h>

// Problem constants
#define BB 4
#define LL 1024
#define DD 768
#define EE 32
#define SS 32
#define HH 3072
#define KK 1024   // E*S

// ---------------- device scratch ----------------
__device__ float g_logits[BB * LL * KK];
__device__ float g_dw[BB * LL * KK];
__device__ __nv_bfloat16 g_xnh[BB * LL * DD],   g_xnl[BB * LL * DD];
__device__ __nv_bfloat16 g_phinh[DD * KK],      g_phinl[DD * KK];
__device__ __nv_bfloat16 g_dwTh[BB * KK * LL],  g_dwTl[BB * KK * LL];
__device__ __nv_bfloat16 g_cwh[BB * LL * KK],   g_cwl[BB * LL * KK];
__device__ __nv_bfloat16 g_sloth[BB * KK * DD], g_slotl[BB * KK * DD];
__device__ __nv_bfloat16 g_hh[BB * KK * HH],    g_hl[BB * KK * HH];
__device__ __nv_bfloat16 g_eoh[BB * KK * DD],   g_eol[BB * KK * DD];

// ---------------- helpers ----------------
__device__ __forceinline__ void split1(float x, __nv_bfloat16& h, __nv_bfloat16& l) {
    h = __float2bfloat16_rn(x);
    l = __float2bfloat16_rn(x - __bfloat162float(h));
}
__device__ __forceinline__ void split_bf16_pack(float x0, float x1, unsigned& hi, unsigned& lo) {
    __nv_bfloat16 h0, l0, h1, l1;
    split1(x0, h0, l0); split1(x1, h1, l1);
    hi = ((unsigned)__bfloat16_as_ushort(h1) << 16) | (unsigned)__bfloat16_as_ushort(h0);
    lo = ((unsigned)__bfloat16_as_ushort(l1) << 16) | (unsigned)__bfloat16_as_ushort(l0);
}
__device__ __forceinline__ void mma_bf16(float* d, const unsigned* a, const unsigned* b) {
    asm volatile(
        "mma.sync.aligned.m16n8k16.row.col.f32.bf16.bf16.f32 "
        "{%0,%1,%2,%3}, {%4,%5,%6,%7}, {%8,%9}, {%0,%1,%2,%3};\n"
        : "+f"(d[0]), "+f"(d[1]), "+f"(d[2]), "+f"(d[3])
        : "r"(a[0]), "r"(a[1]), "r"(a[2]), "r"(a[3]), "r"(b[0]), "r"(b[1]));
}
__device__ __forceinline__ void ldsm_x4(unsigned* r, uint32_t a) {
    asm volatile("ldmatrix.sync.aligned.m8n8.x4.shared.b16 {%0,%1,%2,%3}, [%4];"
                 : "=r"(r[0]), "=r"(r[1]), "=r"(r[2]), "=r"(r[3]) : "r"(a));
}
__device__ __forceinline__ void ldsm_x2_trans(unsigned* r, uint32_t a) {
    asm volatile("ldmatrix.sync.aligned.m8n8.x2.trans.shared.b16 {%0,%1}, [%2];"
                 : "=r"(r[0]), "=r"(r[1]) : "r"(a));
}
__device__ __forceinline__ uint32_t smem_u32(const void* p) {
    return (uint32_t)__cvta_generic_to_shared(p);
}
__device__ __forceinline__ void cp16(uint32_t dst, const void* src) {
    asm volatile("cp.async.cg.shared.global [%0], [%1], 16;" :: "r"(dst), "l"(src));
}
#define CP_COMMIT asm volatile("cp.async.commit_group;" ::: "memory")
#define CP_WAIT0  asm volatile("cp.async.wait_group 0;" ::: "memory")
#define CP_WAIT1  asm volatile("cp.async.wait_group 1;" ::: "memory")

// ---------------- norm / softmax / transpose ----------------
__global__ void norm_x_kernel(const float* __restrict__ x,
                              __nv_bfloat16* __restrict__ oh, __nv_bfloat16* __restrict__ ol) {
    int row = blockIdx.x;
    const float* p = x + (size_t)row * DD;
    float s = 0.f;
    for (int i = threadIdx.x; i < DD; i += 256) { float v = p[i]; s += v * v; }
    __shared__ float sm[8];
    for (int o = 16; o; o >>= 1) s += __shfl_xor_sync(0xffffffffu, s, o);
    if ((threadIdx.x & 31) == 0) sm[threadIdx.x >> 5] = s;
    __syncthreads();
    float tot = 0.f;
#pragma unroll
    for (int i = 0; i < 8; i++) tot += sm[i];
    float inv = 1.f / fmaxf(sqrtf(tot), 1e-12f);
    for (int i = threadIdx.x; i < DD; i += 256) {
        __nv_bfloat16 h, l;
        split1(p[i] * inv, h, l);
        oh[(size_t)row * DD + i] = h;
        ol[(size_t)row * DD + i] = l;
    }
}

__global__ void norm_phi_kernel(const float* __restrict__ phi,
                                const float* __restrict__ scale,
                                __nv_bfloat16* __restrict__ oh, __nv_bfloat16* __restrict__ ol) {
    int k = blockIdx.x;
    float s = 0.f;
    for (int d = threadIdx.x; d < DD; d += 256) { float v = phi[(size_t)d * KK + k]; s += v * v; }
    __shared__ float sm[8];
    for (int o = 16; o; o >>= 1) s += __shfl_xor_sync(0xffffffffu, s, o);
    if ((threadIdx.x & 31) == 0) sm[threadIdx.x >> 5] = s;
    __syncthreads();
    float tot = 0.f;
#pragma unroll
    for (int i = 0; i < 8; i++) tot += sm[i];
    float inv = scale[0] / fmaxf(sqrtf(tot), 1e-12f);
    for (int d = threadIdx.x; d < DD; d += 256) {
        __nv_bfloat16 h, l;
        split1(phi[(size_t)d * KK + k] * inv, h, l);
        oh[(size_t)d * KK + k] = h;
        ol[(size_t)d * KK + k] = l;
    }
}

__global__ void softmax_kernel(const float* __restrict__ logits,
                               float* __restrict__ dw,
                               __nv_bfloat16* __restrict__ cwh, __nv_bfloat16* __restrict__ cwl) {
    int row = blockIdx.x;
    size_t base = (size_t)row * KK;
    int tid = threadIdx.x, lane = tid & 31, wid = tid >> 5;
    float v = logits[base + tid];
    float gmax = v;
    for (int o = 16; o; o >>= 1) gmax = fmaxf(gmax, __shfl_xor_sync(0xffffffffu, gmax, o));
    float ge = expf(v - gmax);
    float gsum = ge;
    for (int o = 16; o; o >>= 1) gsum += __shfl_xor_sync(0xffffffffu, gsum, o);
    dw[base + tid] = ge / gsum;
    __shared__ float wmax[32], wsum[32];
    __shared__ float s_rmax, s_rsum;
    if (lane == 0) wmax[wid] = gmax;
    __syncthreads();
    if (tid < 32) {
        float m = wmax[tid];
        for (int o = 16; o; o >>= 1) m = fmaxf(m, __shfl_xor_sync(0xffffffffu, m, o));
        if (tid == 0) s_rmax = m;
    }
    __syncthreads();
    float e2 = expf(v - s_rmax);
    float ws = e2;
    for (int o = 16; o; o >>= 1) ws += __shfl_xor_sync(0xffffffffu, ws, o);
    if (lane == 0) wsum[wid] = ws;
    __syncthreads();
    if (tid < 32) {
        float t = wsum[tid];
        for (int o = 16; o; o >>= 1) t += __shfl_xor_sync(0xffffffffu, t, o);
        if (tid == 0) s_rsum = t;
    }
    __syncthreads();
    __nv_bfloat16 h, l;
    split1(e2 / s_rsum, h, l);
    cwh[base + tid] = h;
    cwl[base + tid] = l;
}

// dw [b][l][1024] fp32 -> dwT pair [b][slot][l]
__global__ void transpose_split_kernel(const float* __restrict__ dw,
                                       __nv_bfloat16* __restrict__ th,
                                       __nv_bfloat16* __restrict__ tl) {
    __shared__ float t[32][33];
    int b = blockIdx.z;
    int s0 = blockIdx.x * 32, l0 = blockIdx.y * 32;
    int tx = threadIdx.x & 31, ty = threadIdx.x >> 5;  // 32 x 8
    const float* src = dw + (size_t)b * LL * KK;
#pragma unroll
    for (int j = 0; j < 4; j++)
        t[ty + j * 8][tx] = src[(size_t)(l0 + ty + j * 8) * KK + s0 + tx];
    __syncthreads();
    size_t obase = (size_t)b * KK * LL;
#pragma unroll
    for (int j = 0; j < 4; j++) {
        float v = t[tx][ty + j * 8];
        __nv_bfloat16 h, l;
        split1(v, h, l);
        size_t o = obase + (size_t)(s0 + ty + j * 8) * LL + l0 + tx;
        th[o] = h; tl[o] = l;
    }
}

// ============ pair-pair GEMM: 3-stage cp.async ring, 1 sync/tile =============
// buffer b at b*32768: Ah 0, Al 8192, Bh 16384, Bl 24576
#define PP_SMEM 98304

template <bool OUT_PAIR>
__global__ void __launch_bounds__(256, 2) gemm_pp(
    const __nv_bfloat16* __restrict__ Ah, const __nv_bfloat16* __restrict__ Al,
    const __nv_bfloat16* __restrict__ Bh, const __nv_bfloat16* __restrict__ Bl,
    float* __restrict__ C, __nv_bfloat16* __restrict__ Ch, __nv_bfloat16* __restrict__ Cl,
    int M, int N, int K,
    long batchA, long batchB, long batchC) {
    extern __shared__ char smemraw[];
    uint32_t sbase = smem_u32(smemraw);
    size_t zA = (size_t)blockIdx.z * batchA;
    size_t zB = (size_t)blockIdx.z * batchB;
    size_t zC = (size_t)blockIdx.z * batchC;
    int m0 = blockIdx.y * 128, n0 = blockIdx.x * 128;
    int tid = threadIdx.x, lane = tid & 31, wid = tid >> 5;
    int warp_m = wid >> 2, warp_n = wid & 3;
    int g = lane >> 2, tig = lane & 3;
    int mi = lane >> 3, lr = lane & 7;
    int aRow0 = warp_m * 64 + (mi & 1) * 8 + lr;
    int aSel = (aRow0 >> 1) & 3;
    int aKbH = mi >> 1;
    int bmi = mi & 1;

    float acc[4][4][4];
#pragma unroll
    for (int a = 0; a < 4; a++)
#pragma unroll
        for (int b = 0; b < 4; b++)
#pragma unroll
            for (int c = 0; c < 4; c++) acc[a][b][c] = 0.f;

    auto cpTile = [&](int k0, int buf) {
        uint32_t bb = sbase + buf * 32768;
#pragma unroll
        for (int i = 0; i < 4; i++) {
            int idx = i * 256 + tid;
            int plane = idx >> 9, c = idx & 511;
            int m = c >> 2, q = c & 3;
            const __nv_bfloat16* src = (plane ? Al : Ah) + zA + (size_t)(m0 + m) * K + k0 + q * 8;
            cp16(bb + plane * 8192 + m * 64 + (((q ^ ((m >> 1) & 3))) << 4), src);
        }
#pragma unroll
        for (int i = 0; i < 4; i++) {
            int idx = i * 256 + tid;
            int plane = idx >> 9, c = idx & 511;
            int kr = c >> 4, cn = c & 15;
            const __nv_bfloat16* src = (plane ? Bl : Bh) + zB + (size_t)(k0 + kr) * N + n0 + cn * 8;
            cp16(bb + 16384 + plane * 8192 + kr * 256 + ((cn ^ (kr & 7)) << 4), src);
        }
        CP_COMMIT;
    };
    auto mmaTile = [&](int buf) {
        uint32_t bb = sbase + buf * 32768;
#pragma unroll
        for (int ks = 0; ks < 2; ks++) {
            unsigned bHi[4][2], bLo[4][2];
#pragma unroll
            for (int nt = 0; nt < 4; nt++) {
                int kr = ks * 16 + bmi * 8 + lr;
                uint32_t bd = bb + 16384 + (uint32_t)(kr * 256 +
                              (((warp_n * 4 + nt) ^ (kr & 7)) << 4));
                ldsm_x2_trans(bHi[nt], bd);
                ldsm_x2_trans(bLo[nt], bd + 8192);
            }
#pragma unroll
            for (int mt = 0; mt < 4; mt++) {
                unsigned aHi[4], aLo[4];
                uint32_t ad = bb + (uint32_t)((aRow0 + mt * 16) * 64 +
                              (((ks * 2 + aKbH) ^ aSel) << 4));
                ldsm_x4(aHi, ad);
                ldsm_x4(aLo, ad + 8192);
#pragma unroll
                for (int nt = 0; nt < 4; nt++) {
                    mma_bf16(acc[mt][nt], aHi, bLo[nt]);
                    mma_bf16(acc[mt][nt], aLo, bHi[nt]);
                    mma_bf16(acc[mt][nt], aHi, bHi[nt]);
                }
            }
        }
    };

    int KT = K >> 5;
    cpTile(0, 0);
    if (KT > 1) cpTile(32, 1);
    for (int kt = 0; kt < KT; kt++) {
        if (kt + 1 < KT) CP_WAIT1; else CP_WAIT0;  // group kt complete (this thread)
        __syncthreads();                            // publish group kt; mma(kt-1) done everywhere
        if (kt + 2 < KT) cpTile((kt + 2) << 5, (kt + 2) % 3);  // overwrites buf (kt-1)%3: safe
        mmaTile(kt % 3);
    }

#pragma unroll
    for (int mt = 0; mt < 4; mt++)
#pragma unroll
        for (int nt = 0; nt < 4; nt++) {
            int r = m0 + warp_m * 64 + mt * 16 + g;
            int c = n0 + warp_n * 32 + nt * 8 + tig * 2;
#pragma unroll
            for (int half = 0; half < 2; half++) {
                int rr = r + half * 8;
                float v0 = acc[mt][nt][half * 2 + 0];
                float v1 = acc[mt][nt][half * 2 + 1];
                if (OUT_PAIR) {
                    unsigned hi, lo;
                    split_bf16_pack(v0, v1, hi, lo);
                    *(unsigned*)((char*)(Ch + zC) + ((size_t)rr * N + c) * 2) = hi;
                    *(unsigned*)((char*)(Cl + zC) + ((size_t)rr * N + c) * 2) = lo;
                } else {
                    *(float2*)&C[zC + (size_t)rr * N + c] = make_float2(v0, v1);
                }
            }
        }
}

// ============ expert GEMM: A pair (gathered), B fp32 (convert once) ==========
// smem: bufA 2x16KB @0,16384; Bstage fp32 2x16KB @32768,49152; Bplanes 2x16KB @65536,81920
// Race-free 2-sync schedule:
//   S1 sync (mma(kt-1) retired) -> cp(kt+1) -> WAIT(kt) -> convertB(kt)
//   S2 sync (publish planes(kt) + A group kt) -> mma(kt)
#define EX_SMEM 98304

template <bool GELU>
__global__ void __launch_bounds__(256, 2) gemm_expert(
    const __nv_bfloat16* __restrict__ Ah, const __nv_bfloat16* __restrict__ Al,
    const float* __restrict__ B, const float* __restrict__ bias,
    __nv_bfloat16* __restrict__ Ch, __nv_bfloat16* __restrict__ Cl,
    int N, int K, long aBatch, long cBatch) {
    extern __shared__ char smemraw[];
    uint32_t sbase = smem_u32(smemraw);
    int e = blockIdx.z;
    const float* Be = B + (size_t)e * (size_t)K * N;
    const float* biasE = bias + (size_t)e * N;
    int n0 = blockIdx.x * 128;
    int tid = threadIdx.x, lane = tid & 31, wid = tid >> 5;
    int warp_m = wid >> 2, warp_n = wid & 3;
    int g = lane >> 2, tig = lane & 3;
    int mi = lane >> 3, lr = lane & 7;
    int aRow0 = warp_m * 64 + (mi & 1) * 8 + lr;
    int aSel = (aRow0 >> 1) & 3;
    int aKbH = mi >> 1;
    int bmi = mi & 1;

    float acc[4][4][4];
#pragma unroll
    for (int a = 0; a < 4; a++)
#pragma unroll
        for (int b = 0; b < 4; b++)
#pragma unroll
            for (int c = 0; c < 4; c++) acc[a][b][c] = 0.f;

    auto cpTile = [&](int k0, int buf) {
#pragma unroll
        for (int i = 0; i < 4; i++) {
            int idx = i * 256 + tid;
            int plane = idx >> 9, c = idx & 511;
            int m = c >> 2, q = c & 3;
            size_t roff = (size_t)(m >> 5) * aBatch + (size_t)(e * 32 + (m & 31)) * K;
            const __nv_bfloat16* src = (plane ? Al : Ah) + roff + k0 + q * 8;
            cp16(sbase + buf * 16384 + plane * 8192 + m * 64 + ((q ^ ((m >> 1) & 3)) << 4), src);
        }
#pragma unroll
        for (int i = 0; i < 4; i++) {
            int idx = i * 256 + tid;
            int n4 = idx & 31, kr = idx >> 5;
            cp16(sbase + 32768 + buf * 16384 + kr * 512 + n4 * 16,
                 &Be[(size_t)(k0 + kr) * N + n0 + n4 * 4]);
        }
        CP_COMMIT;
    };
    // NOTE: convertB thread->byte map matches cpTile's B map exactly, so each
    // thread reads only bytes its OWN cp.async wrote; per-thread wait suffices.
    auto convertB = [&](int buf) {
        const float* Bs = (const float*)(smemraw + 32768 + buf * 16384);
        char* dst = smemraw + 65536 + buf * 16384;
#pragma unroll
        for (int i = 0; i < 4; i++) {
            int idx = i * 256 + tid;
            int n4 = idx & 31, kr = idx >> 5;
            float4 v = *(const float4*)(Bs + kr * 128 + n4 * 4);
            unsigned h0, l0, h1, l1;
            split_bf16_pack(v.x, v.y, h0, l0);
            split_bf16_pack(v.z, v.w, h1, l1);
            uint32_t off = kr * 256 + (((n4 >> 1) ^ (kr & 7)) << 4) + (n4 & 1) * 8;
            *(uint2*)(dst + off) = make_uint2(h0, h1);
            *(uint2*)(dst + 8192 + off) = make_uint2(l0, l1);
        }
    };
    auto mmaTile = [&](int buf) {
        uint32_t ab = sbase + buf * 16384;
        uint32_t bbb = sbase + 65536 + buf * 16384;
#pragma unroll
        for (int ks = 0; ks < 2; ks++) {
            unsigned bHi[4][2], bLo[4][2];
#pragma unroll
            for (int nt = 0; nt < 4; nt++) {
                int kr = ks * 16 + bmi * 8 + lr;
                uint32_t bd = bbb + (uint32_t)(kr * 256 +
                              (((warp_n * 4 + nt) ^ (kr & 7)) << 4));
                ldsm_x2_trans(bHi[nt], bd);
                ldsm_x2_trans(bLo[nt], bd + 8192);
            }
#pragma unroll
            for (int mt = 0; mt < 4; mt++) {
                unsigned aHi[4], aLo[4];
                uint32_t ad = ab + (uint32_t)((aRow0 + mt * 16) * 64 +
                              (((ks * 2 + aKbH) ^ aSel) << 4));
                ldsm_x4(aHi, ad);
                ldsm_x4(aLo, ad + 8192);
#pragma unroll
                for (int nt = 0; nt < 4; nt++) {
                    mma_bf16(acc[mt][nt], aHi, bLo[nt]);
                    mma_bf16(acc[mt][nt], aLo, bHi[nt]);
                    mma_bf16(acc[mt][nt], aHi, bHi[nt]);
                }
            }
        }
    };

    int KT = K >> 5;
    cpTile(0, 0);
    for (int kt = 0; kt < KT; kt++) {
        __syncthreads();          // S1: mma(kt-1) retired in all warps (no-op at kt=0)
        if (kt + 1 < KT) { cpTile((kt + 1) << 5, (kt + 1) & 1); CP_WAIT1; }
        else CP_WAIT0;            // group kt complete in this thread
        convertB(kt & 1);         // own-thread staged data only
        __syncthreads();          // S2: publish planes(kt) + A group kt
        mmaTile(kt & 1);
    }

#pragma unroll
    for (int mt = 0; mt < 4; mt++)
#pragma unroll
        for (int nt = 0; nt < 4; nt++) {
            int m = warp_m * 64 + mt * 16 + g;
            int c = n0 + warp_n * 32 + nt * 8 + tig * 2;
            float2 bb2 = *(const float2*)&biasE[c];
#pragma unroll
            for (int half = 0; half < 2; half++) {
                int mm = m + half * 8;
                size_t coff = (size_t)(mm >> 5) * cBatch + (size_t)(e * 32 + (mm & 31)) * N;
                float v0 = acc[mt][nt][half * 2 + 0] + bb2.x;
                float v1 = acc[mt][nt][half * 2 + 1] + bb2.y;
                if (GELU) { v0 = v0 * normcdff(v0); v1 = v1 * normcdff(v1); }
                unsigned hi, lo;
                split_bf16_pack(v0, v1, hi, lo);
                *(unsigned*)((char*)Ch + (coff + c) * 2) = hi;
                *(unsigned*)((char*)Cl + (coff + c) * 2) = lo;
            }
        }
}

// ---------------- host launcher ----------------
extern "C" void kernel_launch(void* const* d_in, const int* in_sizes, int n_in,
                              void* d_out, int out_size) {
    const float* x     = (const float*)d_in[0];
    const float* phi   = (const float*)d_in[1];
    const float* scale = (const float*)d_in[2];
    const float* w1    = (const float*)d_in[3];
    const float* b1    = (const float*)d_in[4];
    const float* w2    = (const float*)d_in[5];
    const float* b2    = (const float*)d_in[6];
    float* out = (float*)d_out;

    float *logits, *dw;
    __nv_bfloat16 *xnh, *xnl, *phinh, *phinl, *dwTh, *dwTl, *cwh, *cwl;
    __nv_bfloat16 *sloth, *slotl, *hh, *hl, *eoh, *eol;
    cudaGetSymbolAddress((void**)&logits, g_logits);
    cudaGetSymbolAddress((void**)&dw, g_dw);
    cudaGetSymbolAddress((void**)&xnh, g_xnh);   cudaGetSymbolAddress((void**)&xnl, g_xnl);
    cudaGetSymbolAddress((void**)&phinh, g_phinh); cudaGetSymbolAddress((void**)&phinl, g_phinl);
    cudaGetSymbolAddress((void**)&dwTh, g_dwTh); cudaGetSymbolAddress((void**)&dwTl, g_dwTl);
    cudaGetSymbolAddress((void**)&cwh, g_cwh);   cudaGetSymbolAddress((void**)&cwl, g_cwl);
    cudaGetSymbolAddress((void**)&sloth, g_sloth); cudaGetSymbolAddress((void**)&slotl, g_slotl);
    cudaGetSymbolAddress((void**)&hh, g_hh);     cudaGetSymbolAddress((void**)&hl, g_hl);
    cudaGetSymbolAddress((void**)&eoh, g_eoh);   cudaGetSymbolAddress((void**)&eol, g_eol);

    cudaFuncSetAttribute(gemm_pp<false>, cudaFuncAttributeMaxDynamicSharedMemorySize, PP_SMEM);
    cudaFuncSetAttribute(gemm_pp<true>,  cudaFuncAttributeMaxDynamicSharedMemorySize, PP_SMEM);
    cudaFuncSetAttribute(gemm_expert<true>,  cudaFuncAttributeMaxDynamicSharedMemorySize, EX_SMEM);
    cudaFuncSetAttribute(gemm_expert<false>, cudaFuncAttributeMaxDynamicSharedMemorySize, EX_SMEM);

    // 1) xn pair
    norm_x_kernel<<<BB * LL, 256>>>(x, xnh, xnl);
    // 2) phin pair
    norm_phi_kernel<<<KK, 256>>>(phi, scale, phinh, phinl);
    // 3) logits = xn @ phin  (fp32 out)
    gemm_pp<false><<<dim3(KK / 128, (BB * LL) / 128, 1), 256, PP_SMEM>>>(
        xnh, xnl, phinh, phinl, logits, nullptr, nullptr,
        BB * LL, KK, DD, 0L, 0L, 0L);
    // 4) softmax -> dw fp32 + cw pair
    softmax_kernel<<<BB * LL, 1024>>>(logits, dw, cwh, cwl);
    // 4b) dw -> dwT pair
    transpose_split_kernel<<<dim3(KK / 32, LL / 32, BB), 256>>>(dw, dwTh, dwTl);
    // 5) slots = dwT @ xn  (pair out)
    gemm_pp<true><<<dim3(DD / 128, KK / 128, BB), 256, PP_SMEM>>>(
        dwTh, dwTl, xnh, xnl, nullptr, sloth, slotl,
        KK, DD, LL, (long)(KK * LL), (long)(LL * DD), (long)(KK * DD));
    // 6) h = gelu(slots @ w1 + b1)  (pair out)
    gemm_expert<true><<<dim3(HH / 128, 1, EE), 256, EX_SMEM>>>(
        sloth, slotl, w1, b1, hh, hl, HH, DD, (long)(KK * DD), (long)(KK * HH));
    // 7) eo = h @ w2 + b2  (pair out)
    gemm_expert<false><<<dim3(DD / 128, 1, EE), 256, EX_SMEM>>>(
        hh, hl, w2, b2, eoh, eol, DD, HH, (long)(KK * HH), (long)(KK * DD));
    // 8) out = cw @ eo  (fp32 out)
    gemm_pp<false><<<dim3(DD / 128, LL / 128, BB), 256, PP_SMEM>>>(
        cwh, cwl, eoh, eol, out, nullptr, nullptr,
        LL, DD, KK, (long)(LL * KK), (long)(KK * DD), (long)(LL * DD));
}

// round 13
// speedup vs baseline: 1.0469x; 1.0469x over previous
#include <cuda_runtime.h>
#include <cuda_bf16.h>
#include <math.h>
#include <stdint.h>

// Problem constants
#define BB 4
#define LL 1024
#define DD 768
#define EE 32
#define SS 32
#define HH 3072
#define KK 1024   // E*S

// ---------------- device scratch ----------------
__device__ float g_logits[BB * LL * KK];
__device__ float g_dw[BB * LL * KK];
__device__ __nv_bfloat16 g_xnh[BB * LL * DD],   g_xnl[BB * LL * DD];
__device__ __nv_bfloat16 g_phinh[DD * KK],      g_phinl[DD * KK];
__device__ __nv_bfloat16 g_dwTh[BB * KK * LL],  g_dwTl[BB * KK * LL];
__device__ __nv_bfloat16 g_cwh[BB * LL * KK],   g_cwl[BB * LL * KK];
__device__ __nv_bfloat16 g_sloth[BB * KK * DD], g_slotl[BB * KK * DD];
__device__ __nv_bfloat16 g_hh[BB * KK * HH],    g_hl[BB * KK * HH];
__device__ __nv_bfloat16 g_eoh[BB * KK * DD],   g_eol[BB * KK * DD];

// ---------------- helpers ----------------
__device__ __forceinline__ void split1(float x, __nv_bfloat16& h, __nv_bfloat16& l) {
    h = __float2bfloat16_rn(x);
    l = __float2bfloat16_rn(x - __bfloat162float(h));
}
__device__ __forceinline__ void split_bf16_pack(float x0, float x1, unsigned& hi, unsigned& lo) {
    __nv_bfloat16 h0, l0, h1, l1;
    split1(x0, h0, l0); split1(x1, h1, l1);
    hi = ((unsigned)__bfloat16_as_ushort(h1) << 16) | (unsigned)__bfloat16_as_ushort(h0);
    lo = ((unsigned)__bfloat16_as_ushort(l1) << 16) | (unsigned)__bfloat16_as_ushort(l0);
}
__device__ __forceinline__ void mma_bf16(float* d, const unsigned* a, const unsigned* b) {
    asm volatile(
        "mma.sync.aligned.m16n8k16.row.col.f32.bf16.bf16.f32 "
        "{%0,%1,%2,%3}, {%4,%5,%6,%7}, {%8,%9}, {%0,%1,%2,%3};\n"
        : "+f"(d[0]), "+f"(d[1]), "+f"(d[2]), "+f"(d[3])
        : "r"(a[0]), "r"(a[1]), "r"(a[2]), "r"(a[3]), "r"(b[0]), "r"(b[1]));
}
__device__ __forceinline__ void ldsm_x4(unsigned* r, uint32_t a) {
    asm volatile("ldmatrix.sync.aligned.m8n8.x4.shared.b16 {%0,%1,%2,%3}, [%4];"
                 : "=r"(r[0]), "=r"(r[1]), "=r"(r[2]), "=r"(r[3]) : "r"(a));
}
__device__ __forceinline__ void ldsm_x2_trans(unsigned* r, uint32_t a) {
    asm volatile("ldmatrix.sync.aligned.m8n8.x2.trans.shared.b16 {%0,%1}, [%2];"
                 : "=r"(r[0]), "=r"(r[1]) : "r"(a));
}
__device__ __forceinline__ uint32_t smem_u32(const void* p) {
    return (uint32_t)__cvta_generic_to_shared(p);
}
__device__ __forceinline__ void cp16(uint32_t dst, const void* src) {
    asm volatile("cp.async.cg.shared.global [%0], [%1], 16;" :: "r"(dst), "l"(src));
}
#define CP_COMMIT asm volatile("cp.async.commit_group;" ::: "memory")
#define CP_WAIT0  asm volatile("cp.async.wait_group 0;" ::: "memory")
#define CP_WAIT1  asm volatile("cp.async.wait_group 1;" ::: "memory")

// ---------------- norm kernels ----------------
__global__ void norm_x_kernel(const float* __restrict__ x,
                              __nv_bfloat16* __restrict__ oh, __nv_bfloat16* __restrict__ ol) {
    int row = blockIdx.x;
    const float* p = x + (size_t)row * DD;
    float s = 0.f;
    for (int i = threadIdx.x; i < DD; i += 256) { float v = p[i]; s += v * v; }
    __shared__ float sm[8];
    for (int o = 16; o; o >>= 1) s += __shfl_xor_sync(0xffffffffu, s, o);
    if ((threadIdx.x & 31) == 0) sm[threadIdx.x >> 5] = s;
    __syncthreads();
    float tot = 0.f;
#pragma unroll
    for (int i = 0; i < 8; i++) tot += sm[i];
    float inv = 1.f / fmaxf(sqrtf(tot), 1e-12f);
    for (int i = threadIdx.x; i < DD; i += 256) {
        __nv_bfloat16 h, l;
        split1(p[i] * inv, h, l);
        oh[(size_t)row * DD + i] = h;
        ol[(size_t)row * DD + i] = l;
    }
}

__global__ void norm_phi_kernel(const float* __restrict__ phi,
                                const float* __restrict__ scale,
                                __nv_bfloat16* __restrict__ oh, __nv_bfloat16* __restrict__ ol) {
    int k = blockIdx.x;
    float s = 0.f;
    for (int d = threadIdx.x; d < DD; d += 256) { float v = phi[(size_t)d * KK + k]; s += v * v; }
    __shared__ float sm[8];
    for (int o = 16; o; o >>= 1) s += __shfl_xor_sync(0xffffffffu, s, o);
    if ((threadIdx.x & 31) == 0) sm[threadIdx.x >> 5] = s;
    __syncthreads();
    float tot = 0.f;
#pragma unroll
    for (int i = 0; i < 8; i++) tot += sm[i];
    float inv = scale[0] / fmaxf(sqrtf(tot), 1e-12f);
    for (int d = threadIdx.x; d < DD; d += 256) {
        __nv_bfloat16 h, l;
        split1(phi[(size_t)d * KK + k] * inv, h, l);
        oh[(size_t)d * KK + k] = h;
        ol[(size_t)d * KK + k] = l;
    }
}

// ---------------- softmax: 256 threads, float4/thread, 2 barriers ------------
__global__ void softmax_kernel(const float* __restrict__ logits,
                               float* __restrict__ dw,
                               __nv_bfloat16* __restrict__ cwh, __nv_bfloat16* __restrict__ cwl) {
    int row = blockIdx.x;
    size_t base = (size_t)row * KK;
    int tid = threadIdx.x, lane = tid & 31, wid = tid >> 5;
    float4 v = *(const float4*)&logits[base + tid * 4];
    // group (32 elems = 8 threads) max via width-8 shuffles
    float gm = fmaxf(fmaxf(v.x, v.y), fmaxf(v.z, v.w));
#pragma unroll
    for (int o = 1; o < 8; o <<= 1) gm = fmaxf(gm, __shfl_xor_sync(0xffffffffu, gm, o, 8));
    float e0 = expf(v.x - gm), e1 = expf(v.y - gm), e2v = expf(v.z - gm), e3 = expf(v.w - gm);
    float gs = e0 + e1 + e2v + e3;
#pragma unroll
    for (int o = 1; o < 8; o <<= 1) gs += __shfl_xor_sync(0xffffffffu, gs, o, 8);
    float ginv = 1.f / gs;
    *(float4*)&dw[base + tid * 4] = make_float4(e0 * ginv, e1 * ginv, e2v * ginv, e3 * ginv);
    // row max / row sum as rescale of group results
    __shared__ float wmax[8], wsum[8];
    __shared__ float s_rmax, s_rsum;
    float wm = gm;
#pragma unroll
    for (int o = 8; o < 32; o <<= 1) wm = fmaxf(wm, __shfl_xor_sync(0xffffffffu, wm, o));
    if (lane == 0) wmax[wid] = wm;
    __syncthreads();
    if (tid < 32) {
        float m = (tid < 8) ? wmax[tid] : -1e30f;
#pragma unroll
        for (int o = 4; o; o >>= 1) m = fmaxf(m, __shfl_xor_sync(0xffffffffu, m, o));
        if (tid == 0) s_rmax = m;
    }
    __syncthreads();
    float rmax = s_rmax;
    float gscale = expf(gm - rmax);          // uniform within 8-lane group
    float contrib = ((lane & 7) == 0) ? gs * gscale : 0.f;
#pragma unroll
    for (int o = 16; o; o >>= 1) contrib += __shfl_xor_sync(0xffffffffu, contrib, o);
    if (lane == 0) wsum[wid] = contrib;
    __syncthreads();
    if (tid < 32) {
        float t = (tid < 8) ? wsum[tid] : 0.f;
#pragma unroll
        for (int o = 4; o; o >>= 1) t += __shfl_xor_sync(0xffffffffu, t, o);
        if (tid == 0) s_rsum = t;
    }
    __syncthreads();
    float rinv = gscale / s_rsum;            // e_i(row) = ge_i * gscale / rsum
    unsigned hi0, lo0, hi1, lo1;
    split_bf16_pack(e0 * rinv, e1 * rinv, hi0, lo0);
    split_bf16_pack(e2v * rinv, e3 * rinv, hi1, lo1);
    *(uint2*)((char*)cwh + (base + tid * 4) * 2) = make_uint2(hi0, hi1);
    *(uint2*)((char*)cwl + (base + tid * 4) * 2) = make_uint2(lo0, lo1);
}

// dw [b][l][1024] fp32 -> dwT pair [b][slot][l]
__global__ void transpose_split_kernel(const float* __restrict__ dw,
                                       __nv_bfloat16* __restrict__ th,
                                       __nv_bfloat16* __restrict__ tl) {
    __shared__ float t[32][33];
    int b = blockIdx.z;
    int s0 = blockIdx.x * 32, l0 = blockIdx.y * 32;
    int tx = threadIdx.x & 31, ty = threadIdx.x >> 5;  // 32 x 8
    const float* src = dw + (size_t)b * LL * KK;
#pragma unroll
    for (int j = 0; j < 4; j++)
        t[ty + j * 8][tx] = src[(size_t)(l0 + ty + j * 8) * KK + s0 + tx];
    __syncthreads();
    size_t obase = (size_t)b * KK * LL;
#pragma unroll
    for (int j = 0; j < 4; j++) {
        float v = t[tx][ty + j * 8];
        __nv_bfloat16 h, l;
        split1(v, h, l);
        size_t o = obase + (size_t)(s0 + ty + j * 8) * LL + l0 + tx;
        th[o] = h; tl[o] = l;
    }
}

// ============ pair-pair GEMM (R10 schedule: double buffer, 2 syncs/tile) =====
// buffer b at b*32768: Ah 0, Al 8192, Bh 16384, Bl 24576
#define PP_SMEM 65536

template <bool OUT_PAIR>
__global__ void __launch_bounds__(256, 2) gemm_pp(
    const __nv_bfloat16* __restrict__ Ah, const __nv_bfloat16* __restrict__ Al,
    const __nv_bfloat16* __restrict__ Bh, const __nv_bfloat16* __restrict__ Bl,
    float* __restrict__ C, __nv_bfloat16* __restrict__ Ch, __nv_bfloat16* __restrict__ Cl,
    int M, int N, int K,
    long batchA, long batchB, long batchC) {
    extern __shared__ char smemraw[];
    uint32_t sbase = smem_u32(smemraw);
    size_t zA = (size_t)blockIdx.z * batchA;
    size_t zB = (size_t)blockIdx.z * batchB;
    size_t zC = (size_t)blockIdx.z * batchC;
    int m0 = blockIdx.y * 128, n0 = blockIdx.x * 128;
    int tid = threadIdx.x, lane = tid & 31, wid = tid >> 5;
    int warp_m = wid >> 2, warp_n = wid & 3;
    int g = lane >> 2, tig = lane & 3;
    int mi = lane >> 3, lr = lane & 7;
    int aRow0 = warp_m * 64 + (mi & 1) * 8 + lr;
    int aSel = (aRow0 >> 1) & 3;
    int aKbH = mi >> 1;
    int bmi = mi & 1;

    float acc[4][4][4];
#pragma unroll
    for (int a = 0; a < 4; a++)
#pragma unroll
        for (int b = 0; b < 4; b++)
#pragma unroll
            for (int c = 0; c < 4; c++) acc[a][b][c] = 0.f;

    auto cpTile = [&](int k0, int buf) {
        uint32_t bb = sbase + buf * 32768;
#pragma unroll
        for (int i = 0; i < 4; i++) {
            int idx = i * 256 + tid;
            int plane = idx >> 9, c = idx & 511;
            int m = c >> 2, q = c & 3;
            const __nv_bfloat16* src = (plane ? Al : Ah) + zA + (size_t)(m0 + m) * K + k0 + q * 8;
            cp16(bb + plane * 8192 + m * 64 + (((q ^ ((m >> 1) & 3))) << 4), src);
        }
#pragma unroll
        for (int i = 0; i < 4; i++) {
            int idx = i * 256 + tid;
            int plane = idx >> 9, c = idx & 511;
            int kr = c >> 4, cn = c & 15;
            const __nv_bfloat16* src = (plane ? Bl : Bh) + zB + (size_t)(k0 + kr) * N + n0 + cn * 8;
            cp16(bb + 16384 + plane * 8192 + kr * 256 + ((cn ^ (kr & 7)) << 4), src);
        }
        CP_COMMIT;
    };
    auto mmaTile = [&](int buf) {
        uint32_t bb = sbase + buf * 32768;
#pragma unroll
        for (int ks = 0; ks < 2; ks++) {
            unsigned bHi[4][2], bLo[4][2];
#pragma unroll
            for (int nt = 0; nt < 4; nt++) {
                int kr = ks * 16 + bmi * 8 + lr;
                uint32_t bd = bb + 16384 + (uint32_t)(kr * 256 +
                              (((warp_n * 4 + nt) ^ (kr & 7)) << 4));
                ldsm_x2_trans(bHi[nt], bd);
                ldsm_x2_trans(bLo[nt], bd + 8192);
            }
#pragma unroll
            for (int mt = 0; mt < 4; mt++) {
                unsigned aHi[4], aLo[4];
                uint32_t ad = bb + (uint32_t)((aRow0 + mt * 16) * 64 +
                              (((ks * 2 + aKbH) ^ aSel) << 4));
                ldsm_x4(aHi, ad);
                ldsm_x4(aLo, ad + 8192);
#pragma unroll
                for (int nt = 0; nt < 4; nt++) {
                    mma_bf16(acc[mt][nt], aHi, bLo[nt]);
                    mma_bf16(acc[mt][nt], aLo, bHi[nt]);
                    mma_bf16(acc[mt][nt], aHi, bHi[nt]);
                }
            }
        }
    };

    int KT = K >> 5;
    cpTile(0, 0);
    for (int kt = 0; kt < KT; kt++) {
        if (kt + 1 < KT) { cpTile((kt + 1) << 5, (kt + 1) & 1); CP_WAIT1; }
        else CP_WAIT0;
        __syncthreads();
        mmaTile(kt & 1);
        __syncthreads();
    }

#pragma unroll
    for (int mt = 0; mt < 4; mt++)
#pragma unroll
        for (int nt = 0; nt < 4; nt++) {
            int r = m0 + warp_m * 64 + mt * 16 + g;
            int c = n0 + warp_n * 32 + nt * 8 + tig * 2;
#pragma unroll
            for (int half = 0; half < 2; half++) {
                int rr = r + half * 8;
                float v0 = acc[mt][nt][half * 2 + 0];
                float v1 = acc[mt][nt][half * 2 + 1];
                if (OUT_PAIR) {
                    unsigned hi, lo;
                    split_bf16_pack(v0, v1, hi, lo);
                    *(unsigned*)((char*)(Ch + zC) + ((size_t)rr * N + c) * 2) = hi;
                    *(unsigned*)((char*)(Cl + zC) + ((size_t)rr * N + c) * 2) = lo;
                } else {
                    *(float2*)&C[zC + (size_t)rr * N + c] = make_float2(v0, v1);
                }
            }
        }
}

// ============ expert GEMM (R10 schedule: double buffer, 3 syncs/tile) ========
// smem: bufA 2x16KB @0,16384; Bstage fp32 2x16KB @32768,49152; Bplanes 2x16KB @65536,81920
#define EX_SMEM 98304

template <bool GELU>
__global__ void __launch_bounds__(256, 2) gemm_expert(
    const __nv_bfloat16* __restrict__ Ah, const __nv_bfloat16* __restrict__ Al,
    const float* __restrict__ B, const float* __restrict__ bias,
    __nv_bfloat16* __restrict__ Ch, __nv_bfloat16* __restrict__ Cl,
    int N, int K, long aBatch, long cBatch) {
    extern __shared__ char smemraw[];
    uint32_t sbase = smem_u32(smemraw);
    int e = blockIdx.z;
    const float* Be = B + (size_t)e * (size_t)K * N;
    const float* biasE = bias + (size_t)e * N;
    int n0 = blockIdx.x * 128;
    int tid = threadIdx.x, lane = tid & 31, wid = tid >> 5;
    int warp_m = wid >> 2, warp_n = wid & 3;
    int g = lane >> 2, tig = lane & 3;
    int mi = lane >> 3, lr = lane & 7;
    int aRow0 = warp_m * 64 + (mi & 1) * 8 + lr;
    int aSel = (aRow0 >> 1) & 3;
    int aKbH = mi >> 1;
    int bmi = mi & 1;

    float acc[4][4][4];
#pragma unroll
    for (int a = 0; a < 4; a++)
#pragma unroll
        for (int b = 0; b < 4; b++)
#pragma unroll
            for (int c = 0; c < 4; c++) acc[a][b][c] = 0.f;

    auto cpTile = [&](int k0, int buf) {
#pragma unroll
        for (int i = 0; i < 4; i++) {
            int idx = i * 256 + tid;
            int plane = idx >> 9, c = idx & 511;
            int m = c >> 2, q = c & 3;
            size_t roff = (size_t)(m >> 5) * aBatch + (size_t)(e * 32 + (m & 31)) * K;
            const __nv_bfloat16* src = (plane ? Al : Ah) + roff + k0 + q * 8;
            cp16(sbase + buf * 16384 + plane * 8192 + m * 64 + ((q ^ ((m >> 1) & 3)) << 4), src);
        }
#pragma unroll
        for (int i = 0; i < 4; i++) {
            int idx = i * 256 + tid;
            int n4 = idx & 31, kr = idx >> 5;
            cp16(sbase + 32768 + buf * 16384 + kr * 512 + n4 * 16,
                 &Be[(size_t)(k0 + kr) * N + n0 + n4 * 4]);
        }
        CP_COMMIT;
    };
    auto convertB = [&](int buf) {
        const float* Bs = (const float*)(smemraw + 32768 + buf * 16384);
        char* dst = smemraw + 65536 + buf * 16384;
#pragma unroll
        for (int i = 0; i < 4; i++) {
            int idx = i * 256 + tid;
            int n4 = idx & 31, kr = idx >> 5;
            float4 v = *(const float4*)(Bs + kr * 128 + n4 * 4);
            unsigned h0, l0, h1, l1;
            split_bf16_pack(v.x, v.y, h0, l0);
            split_bf16_pack(v.z, v.w, h1, l1);
            uint32_t off = kr * 256 + (((n4 >> 1) ^ (kr & 7)) << 4) + (n4 & 1) * 8;
            *(uint2*)(dst + off) = make_uint2(h0, h1);
            *(uint2*)(dst + 8192 + off) = make_uint2(l0, l1);
        }
    };
    auto mmaTile = [&](int buf) {
        uint32_t ab = sbase + buf * 16384;
        uint32_t bbb = sbase + 65536 + buf * 16384;
#pragma unroll
        for (int ks = 0; ks < 2; ks++) {
            unsigned bHi[4][2], bLo[4][2];
#pragma unroll
            for (int nt = 0; nt < 4; nt++) {
                int kr = ks * 16 + bmi * 8 + lr;
                uint32_t bd = bbb + (uint32_t)(kr * 256 +
                              (((warp_n * 4 + nt) ^ (kr & 7)) << 4));
                ldsm_x2_trans(bHi[nt], bd);
                ldsm_x2_trans(bLo[nt], bd + 8192);
            }
#pragma unroll
            for (int mt = 0; mt < 4; mt++) {
                unsigned aHi[4], aLo[4];
                uint32_t ad = ab + (uint32_t)((aRow0 + mt * 16) * 64 +
                              (((ks * 2 + aKbH) ^ aSel) << 4));
                ldsm_x4(aHi, ad);
                ldsm_x4(aLo, ad + 8192);
#pragma unroll
                for (int nt = 0; nt < 4; nt++) {
                    mma_bf16(acc[mt][nt], aHi, bLo[nt]);
                    mma_bf16(acc[mt][nt], aLo, bHi[nt]);
                    mma_bf16(acc[mt][nt], aHi, bHi[nt]);
                }
            }
        }
    };

    int KT = K >> 5;
    cpTile(0, 0);
    for (int kt = 0; kt < KT; kt++) {
        if (kt + 1 < KT) { cpTile((kt + 1) << 5, (kt + 1) & 1); CP_WAIT1; }
        else CP_WAIT0;
        __syncthreads();
        convertB(kt & 1);
        __syncthreads();
        mmaTile(kt & 1);
        __syncthreads();
    }

#pragma unroll
    for (int mt = 0; mt < 4; mt++)
#pragma unroll
        for (int nt = 0; nt < 4; nt++) {
            int m = warp_m * 64 + mt * 16 + g;
            int c = n0 + warp_n * 32 + nt * 8 + tig * 2;
            float2 bb2 = *(const float2*)&biasE[c];
#pragma unroll
            for (int half = 0; half < 2; half++) {
                int mm = m + half * 8;
                size_t coff = (size_t)(mm >> 5) * cBatch + (size_t)(e * 32 + (mm & 31)) * N;
                float v0 = acc[mt][nt][half * 2 + 0] + bb2.x;
                float v1 = acc[mt][nt][half * 2 + 1] + bb2.y;
                if (GELU) { v0 = v0 * normcdff(v0); v1 = v1 * normcdff(v1); }
                unsigned hi, lo;
                split_bf16_pack(v0, v1, hi, lo);
                *(unsigned*)((char*)Ch + (coff + c) * 2) = hi;
                *(unsigned*)((char*)Cl + (coff + c) * 2) = lo;
            }
        }
}

// ---------------- host launcher ----------------
extern "C" void kernel_launch(void* const* d_in, const int* in_sizes, int n_in,
                              void* d_out, int out_size) {
    const float* x     = (const float*)d_in[0];
    const float* phi   = (const float*)d_in[1];
    const float* scale = (const float*)d_in[2];
    const float* w1    = (const float*)d_in[3];
    const float* b1    = (const float*)d_in[4];
    const float* w2    = (const float*)d_in[5];
    const float* b2    = (const float*)d_in[6];
    float* out = (float*)d_out;

    float *logits, *dw;
    __nv_bfloat16 *xnh, *xnl, *phinh, *phinl, *dwTh, *dwTl, *cwh, *cwl;
    __nv_bfloat16 *sloth, *slotl, *hh, *hl, *eoh, *eol;
    cudaGetSymbolAddress((void**)&logits, g_logits);
    cudaGetSymbolAddress((void**)&dw, g_dw);
    cudaGetSymbolAddress((void**)&xnh, g_xnh);   cudaGetSymbolAddress((void**)&xnl, g_xnl);
    cudaGetSymbolAddress((void**)&phinh, g_phinh); cudaGetSymbolAddress((void**)&phinl, g_phinl);
    cudaGetSymbolAddress((void**)&dwTh, g_dwTh); cudaGetSymbolAddress((void**)&dwTl, g_dwTl);
    cudaGetSymbolAddress((void**)&cwh, g_cwh);   cudaGetSymbolAddress((void**)&cwl, g_cwl);
    cudaGetSymbolAddress((void**)&sloth, g_sloth); cudaGetSymbolAddress((void**)&slotl, g_slotl);
    cudaGetSymbolAddress((void**)&hh, g_hh);     cudaGetSymbolAddress((void**)&hl, g_hl);
    cudaGetSymbolAddress((void**)&eoh, g_eoh);   cudaGetSymbolAddress((void**)&eol, g_eol);

    cudaFuncSetAttribute(gemm_pp<false>, cudaFuncAttributeMaxDynamicSharedMemorySize, PP_SMEM);
    cudaFuncSetAttribute(gemm_pp<true>,  cudaFuncAttributeMaxDynamicSharedMemorySize, PP_SMEM);
    cudaFuncSetAttribute(gemm_expert<true>,  cudaFuncAttributeMaxDynamicSharedMemorySize, EX_SMEM);
    cudaFuncSetAttribute(gemm_expert<false>, cudaFuncAttributeMaxDynamicSharedMemorySize, EX_SMEM);

    // 1) xn pair
    norm_x_kernel<<<BB * LL, 256>>>(x, xnh, xnl);
    // 2) phin pair
    norm_phi_kernel<<<KK, 256>>>(phi, scale, phinh, phinl);
    // 3) logits = xn @ phin  (fp32 out)
    gemm_pp<false><<<dim3(KK / 128, (BB * LL) / 128, 1), 256, PP_SMEM>>>(
        xnh, xnl, phinh, phinl, logits, nullptr, nullptr,
        BB * LL, KK, DD, 0L, 0L, 0L);
    // 4) softmax -> dw fp32 + cw pair  (256 threads/row)
    softmax_kernel<<<BB * LL, 256>>>(logits, dw, cwh, cwl);
    // 4b) dw -> dwT pair
    transpose_split_kernel<<<dim3(KK / 32, LL / 32, BB), 256>>>(dw, dwTh, dwTl);
    // 5) slots = dwT @ xn  (pair out)
    gemm_pp<true><<<dim3(DD / 128, KK / 128, BB), 256, PP_SMEM>>>(
        dwTh, dwTl, xnh, xnl, nullptr, sloth, slotl,
        KK, DD, LL, (long)(KK * LL), (long)(LL * DD), (long)(KK * DD));
    // 6) h = gelu(slots @ w1 + b1)  (pair out)
    gemm_expert<true><<<dim3(HH / 128, 1, EE), 256, EX_SMEM>>>(
        sloth, slotl, w1, b1, hh, hl, HH, DD, (long)(KK * DD), (long)(KK * HH));
    // 7) eo = h @ w2 + b2  (pair out)
    gemm_expert<false><<<dim3(DD / 128, 1, EE), 256, EX_SMEM>>>(
        hh, hl, w2, b2, eoh, eol, DD, HH, (long)(KK * HH), (long)(KK * DD));
    // 8) out = cw @ eo  (fp32 out)
    gemm_pp<false><<<dim3(DD / 128, LL / 128, BB), 256, PP_SMEM>>>(
        cwh, cwl, eoh, eol, out, nullptr, nullptr,
        LL, DD, KK, (long)(LL * KK), (long)(KK * DD), (long)(LL * DD));
}